// round 9
// baseline (speedup 1.0000x reference)
#include <cuda_runtime.h>
#include <cuda_fp16.h>
#include <math.h>
#include <stdint.h>

// ---- problem constants ----
#define NL 12
#define NH 12
#define NC 768
#define NV 50257
#define NT 1024
#define NB 4
#define ND 64
#define NTOK (NB * NT)   // 4096

// ---- activation scratch ----
__device__ float g_x[NTOK * NC];          // residual stream
__device__ float g_qkv[NTOK * 3 * NC];    // qkv (fp32, read by attn)
__device__ __half g_xh[NTOK * NC],     g_xl[NTOK * NC];      // act fp16 planes (768)
__device__ __half g_yh[NTOK * 4 * NC], g_yl[NTOK * 4 * NC];  // act fp16 planes (3072)
__device__ float g_af[NTOK * NC];         // act fp32 (768-wide A sources)
__device__ float g_af2[NTOK * 4 * NC];    // act fp32 (fc output, 3072-wide)

// ---- weights: fp16 hi/lo planes + fp32, all [N][K] layout ----
__device__ __half g_wa_h[12 * 2304 * 768], g_wa_l[12 * 2304 * 768];
__device__ __half g_wp_h[12 * 768 * 768],  g_wp_l[12 * 768 * 768];
__device__ __half g_wf_h[12 * 3072 * 768], g_wf_l[12 * 3072 * 768];
__device__ __half g_wq_h[12 * 768 * 3072], g_wq_l[12 * 768 * 3072];
__device__ __half g_lm_h[50257 * 768],     g_lm_l[50257 * 768];
__device__ float  g_wa_f[12 * 2304 * 768];
__device__ float  g_wp_f[12 * 768 * 768];
__device__ float  g_wf_f[12 * 3072 * 768];
__device__ float  g_wq_f[12 * 768 * 3072];

// =====================================================================
// helpers
// =====================================================================
__device__ __forceinline__ uint32_t smem_u32(const void* p) {
    uint32_t a;
    asm("{ .reg .u64 t; cvta.to.shared.u64 t, %1; cvt.u32.u64 %0, t; }"
        : "=r"(a) : "l"(p));
    return a;
}
__device__ __forceinline__ void cpa16(uint32_t dst, const void* src) {
    asm volatile("cp.async.cg.shared.global [%0], [%1], 16;"
                 :: "r"(dst), "l"(src));
}
__device__ __forceinline__ uint32_t swz(uint32_t o) {   // SW128-style swizzle
    return o ^ ((o >> 3) & 0x70);
}
__device__ __forceinline__ float gelu_f(float u) {
    return 0.5f * u * (1.0f + tanhf(0.7978845608028654f * (u + 0.044715f * u * u * u)));
}
__device__ __forceinline__ void split_h(float v, __half& hi, __half& lo) {
    hi = __float2half_rn(v);
    lo = __float2half_rn(v - __half2float(hi));
}
__device__ __forceinline__ void mma_f16(float* c, const unsigned* a,
                                        unsigned b0, unsigned b1) {
    asm volatile(
        "mma.sync.aligned.m16n8k16.row.col.f32.f16.f16.f32 "
        "{%0,%1,%2,%3}, {%4,%5,%6,%7}, {%8,%9}, {%0,%1,%2,%3};"
        : "+f"(c[0]), "+f"(c[1]), "+f"(c[2]), "+f"(c[3])
        : "r"(a[0]), "r"(a[1]), "r"(a[2]), "r"(a[3]), "r"(b0), "r"(b1));
}

// =====================================================================
// weight conversion: transpose [K][N] fp32 -> [N][K] {fp16 hi, fp16 lo, fp32}
// =====================================================================
__global__ void transpose_split(const float* __restrict__ W,
                                __half* __restrict__ OH, __half* __restrict__ OL,
                                float* __restrict__ OF, int K, int N) {
    __shared__ float t[32][33];
    int l = blockIdx.z;
    const float* Wl = W + (size_t)l * K * N;
    __half* OHl = OH + (size_t)l * K * N;
    __half* OLl = OL + (size_t)l * K * N;
    float*  OFl = OF + (size_t)l * K * N;
    int n0 = blockIdx.x * 32, k0 = blockIdx.y * 32;
    int tx = threadIdx.x, ty = threadIdx.y;
    #pragma unroll
    for (int i = ty; i < 32; i += 8)
        t[i][tx] = Wl[(size_t)(k0 + i) * N + n0 + tx];
    __syncthreads();
    #pragma unroll
    for (int i = ty; i < 32; i += 8) {
        float v = t[tx][i];
        __half h, lo;
        split_h(v, h, lo);
        size_t o = (size_t)(n0 + i) * K + k0 + tx;
        OHl[o] = h;
        OLl[o] = lo;
        OFl[o] = v;
    }
}

// lm_head already [N][K] fp32: fp16 split only
__global__ void split_kernel(const float* __restrict__ W,
                             __half* __restrict__ H, __half* __restrict__ L,
                             int n) {
    int i = blockIdx.x * blockDim.x + threadIdx.x;
    if (i < n) {
        __half h, lo;
        split_h(W[i], h, lo);
        H[i] = h;
        L[i] = lo;
    }
}

// =====================================================================
// embedding
// =====================================================================
__global__ void embed_kernel(const int* __restrict__ idx,
                             const float* __restrict__ wte,
                             const float* __restrict__ wpe,
                             float* __restrict__ x) {
    int row = blockIdx.x;
    int t = row % NT;
    int tok = idx[row];
    const float* we = wte + (size_t)tok * NC;
    const float* wp = wpe + (size_t)t * NC;
    float* out = x + (size_t)row * NC;
    for (int c = threadIdx.x; c < NC; c += blockDim.x)
        out[c] = we[c] + wp[c];
}

// =====================================================================
// layernorm -> fp16 hi/lo planes + fp32 copy
// =====================================================================
__global__ void ln_kernel(const float* __restrict__ x,
                          const float* __restrict__ w,
                          const float* __restrict__ b,
                          __half* __restrict__ oh, __half* __restrict__ ol,
                          float* __restrict__ of) {
    int row = blockIdx.x;
    const float* xr = x + (size_t)row * NC;
    __shared__ float red[32];
    int tid = threadIdx.x;
    int nwarp = blockDim.x >> 5;

    float s = 0.f;
    for (int c = tid; c < NC; c += blockDim.x) s += xr[c];
    #pragma unroll
    for (int o = 16; o; o >>= 1) s += __shfl_xor_sync(0xffffffffu, s, o);
    if ((tid & 31) == 0) red[tid >> 5] = s;
    __syncthreads();
    if (tid < 32) {
        float v = (tid < nwarp) ? red[tid] : 0.f;
        #pragma unroll
        for (int o = 16; o; o >>= 1) v += __shfl_xor_sync(0xffffffffu, v, o);
        if (tid == 0) red[0] = v;
    }
    __syncthreads();
    float mu = red[0] * (1.0f / NC);
    __syncthreads();

    float s2 = 0.f;
    for (int c = tid; c < NC; c += blockDim.x) {
        float d = xr[c] - mu;
        s2 += d * d;
    }
    #pragma unroll
    for (int o = 16; o; o >>= 1) s2 += __shfl_xor_sync(0xffffffffu, s2, o);
    if ((tid & 31) == 0) red[tid >> 5] = s2;
    __syncthreads();
    if (tid < 32) {
        float v = (tid < nwarp) ? red[tid] : 0.f;
        #pragma unroll
        for (int o = 16; o; o >>= 1) v += __shfl_xor_sync(0xffffffffu, v, o);
        if (tid == 0) red[0] = v;
    }
    __syncthreads();
    float var = red[0] * (1.0f / NC);
    float rstd = rsqrtf(var + 1e-5f);
    for (int c = tid; c < NC; c += blockDim.x) {
        float v = (xr[c] - mu) * rstd * w[c] + b[c];
        __half h, lo;
        split_h(v, h, lo);
        oh[(size_t)row * NC + c] = h;
        ol[(size_t)row * NC + c] = lo;
        of[(size_t)row * NC + c] = v;
    }
}

// =====================================================================
// HYBRID GEMM (NT): C[M,N] = A[M,K] @ B[N,K]^T
//   warps 0-3 : tensor pipe, rows 0..31, 3-pass fp16 split mma
//   warps 4-11: FMA pipe, rows 32..127, exact fp32 SIMT
// CTA tile 128x128, K stages of 64, double-buffered cp.async smem.
// =====================================================================
#define OAH 0          // fp16 hi A rows 0..31   (4 KB, SW128)
#define OAL 4096       // fp16 lo A rows 0..31   (4 KB)
#define OBH 8192       // fp16 hi B 128 rows     (16 KB)
#define OBL 24576      // fp16 lo B 128 rows     (16 KB)
#define OAF 40960      // fp32 A rows 32..127, 272B/row (26112 B)
#define OBF 67072      // fp32 B 128 rows, 272B/row     (34816 B)
#define STAGE_B 101888
#define GSMEM_BYTES (2 * STAGE_B + 1024)

__device__ __forceinline__ void stage_load(uint32_t sb,
        const __half* Ah, const __half* Al, const float* Af,
        const __half* Bh, const __half* Bl, const float* Bf,
        int bm, int bn, int N, int K, int k0, int tid) {
    #pragma unroll
    for (int i = 0; i < 16; i++) {
        int id = i * 384 + tid;                 // 0..6143
        if (id < 512) {                         // Ah / Al (rows 0..31)
            int p = id >> 8, t = id & 255;
            int row = t >> 3, c16 = t & 7;
            cpa16(sb + (p ? OAL : OAH) + swz((uint32_t)(row * 128 + c16 * 16)),
                  (p ? Al : Ah) + (size_t)(bm + row) * K + k0 + c16 * 8);
        } else if (id < 2560) {                 // Bh / Bl (rows 0..127)
            int t = id - 512;
            int p = t >> 10; t &= 1023;
            int row = t >> 3, c16 = t & 7;
            int gn = bn + row;
            if (gn < N)
                cpa16(sb + (p ? OBL : OBH) + swz((uint32_t)(row * 128 + c16 * 16)),
                      (p ? Bl : Bh) + (size_t)gn * K + k0 + c16 * 8);
        } else if (id < 4096) {                 // Af (rows 32..127, fp32)
            int t = id - 2560;
            int row = t >> 4, q = t & 15;
            cpa16(sb + OAF + row * 272 + q * 16,
                  Af + (size_t)(bm + 32 + row) * K + k0 + q * 4);
        } else {                                // Bf (rows 0..127, fp32)
            int t = id - 4096;
            int row = t >> 4, q = t & 15;
            int gn = bn + row;
            if (gn < N)
                cpa16(sb + OBF + row * 272 + q * 16,
                      Bf + (size_t)gn * K + k0 + q * 4);
        }
    }
}

__device__ __forceinline__ void emit_out(float v, int row, int col, int N,
        const float* bias, const float* res, int act,
        float* Cf, __half* Ch, __half* Cl, float* Caf) {
    if (col >= N) return;
    if (bias) v += bias[col];
    if (act) v = gelu_f(v);
    if (Ch) {
        __half h, lo;
        split_h(v, h, lo);
        Ch[(size_t)row * N + col] = h;
        Cl[(size_t)row * N + col] = lo;
        Caf[(size_t)row * N + col] = v;
    } else {
        if (res) v += res[(size_t)row * N + col];
        Cf[(size_t)row * N + col] = v;
    }
}

__global__ void __launch_bounds__(384) hyb_gemm(
    const __half* __restrict__ Ah, const __half* __restrict__ Al,
    const float* __restrict__ Af,
    const __half* __restrict__ Bh, const __half* __restrict__ Bl,
    const float* __restrict__ Bf,
    const float* __restrict__ bias, const float* __restrict__ res,
    float* __restrict__ Cf, __half* __restrict__ Ch, __half* __restrict__ Cl,
    float* __restrict__ Caf,
    int M, int N, int K, int act)
{
    extern __shared__ char dsm[];
    uint32_t sb0 = (smem_u32(dsm) + 1023) & ~1023u;
    const char* sm0 = dsm + (sb0 - smem_u32(dsm));

    int tid = threadIdx.x;
    int lane = tid & 31, warp = tid >> 5;
    int bm = blockIdx.x * 128;
    int bn = blockIdx.y * 128;
    const int S = K / 64;

    // tensor-warp state
    int g = lane >> 2, t4 = lane & 3;
    int wn = warp * 32;                   // valid for warps 0-3
    float c[2][4][4] = {};
    // SIMT-warp state
    int ws = warp - 4;                    // valid for warps 4-11
    int lr0 = ws * 12;
    float acc[12][4] = {};

    stage_load(sb0, Ah, Al, Af, Bh, Bl, Bf, bm, bn, N, K, 0, tid);
    asm volatile("cp.async.commit_group;");

    for (int s = 0; s < S; s++) {
        if (s + 1 < S) {
            stage_load(sb0 + ((s + 1) & 1) * STAGE_B, Ah, Al, Af, Bh, Bl, Bf,
                       bm, bn, N, K, (s + 1) * 64, tid);
            asm volatile("cp.async.commit_group;");
            asm volatile("cp.async.wait_group 1;");
        } else {
            asm volatile("cp.async.wait_group 0;");
        }
        __syncthreads();

        const char* st = sm0 + (s & 1) * STAGE_B;

        if (warp < 4) {
            // ---- tensor pipe: rows 0..31, cols wn..wn+31, 3-pass split ----
            #pragma unroll
            for (int kk = 0; kk < 4; kk++) {
                int kw = kk * 8;
                unsigned ah[2][4], al[2][4];
                #pragma unroll
                for (int im = 0; im < 2; im++) {
                    int r0 = im * 16 + g, r8 = r0 + 8;
                    ah[im][0] = *(const unsigned*)(st + OAH + swz(r0 * 128 + (kw + t4) * 4));
                    ah[im][1] = *(const unsigned*)(st + OAH + swz(r8 * 128 + (kw + t4) * 4));
                    ah[im][2] = *(const unsigned*)(st + OAH + swz(r0 * 128 + (kw + 4 + t4) * 4));
                    ah[im][3] = *(const unsigned*)(st + OAH + swz(r8 * 128 + (kw + 4 + t4) * 4));
                    al[im][0] = *(const unsigned*)(st + OAL + swz(r0 * 128 + (kw + t4) * 4));
                    al[im][1] = *(const unsigned*)(st + OAL + swz(r8 * 128 + (kw + t4) * 4));
                    al[im][2] = *(const unsigned*)(st + OAL + swz(r0 * 128 + (kw + 4 + t4) * 4));
                    al[im][3] = *(const unsigned*)(st + OAL + swz(r8 * 128 + (kw + 4 + t4) * 4));
                }
                #pragma unroll
                for (int jn = 0; jn < 4; jn++) {
                    int n = wn + jn * 8 + g;
                    unsigned bh0 = *(const unsigned*)(st + OBH + swz(n * 128 + (kw + t4) * 4));
                    unsigned bh1 = *(const unsigned*)(st + OBH + swz(n * 128 + (kw + 4 + t4) * 4));
                    unsigned bl0 = *(const unsigned*)(st + OBL + swz(n * 128 + (kw + t4) * 4));
                    unsigned bl1 = *(const unsigned*)(st + OBL + swz(n * 128 + (kw + 4 + t4) * 4));
                    #pragma unroll
                    for (int im = 0; im < 2; im++) {
                        mma_f16(c[im][jn], ah[im], bh0, bh1);
                        mma_f16(c[im][jn], ah[im], bl0, bl1);
                        mma_f16(c[im][jn], al[im], bh0, bh1);
                    }
                }
            }
        } else {
            // ---- FMA pipe: rows 32..127, exact fp32 ----
            const float4* afp = (const float4*)(st + OAF);  // 17 float4 per row
            const float4* bfp = (const float4*)(st + OBF);
            #pragma unroll 4
            for (int kq = 0; kq < 16; kq++) {
                float4 b4[4];
                #pragma unroll
                for (int j = 0; j < 4; j++)
                    b4[j] = bfp[(lane + 32 * j) * 17 + kq];
                #pragma unroll
                for (int r = 0; r < 12; r++) {
                    float4 a4 = afp[(lr0 + r) * 17 + kq];
                    #pragma unroll
                    for (int j = 0; j < 4; j++) {
                        acc[r][j] = fmaf(a4.x, b4[j].x, acc[r][j]);
                        acc[r][j] = fmaf(a4.y, b4[j].y, acc[r][j]);
                        acc[r][j] = fmaf(a4.z, b4[j].z, acc[r][j]);
                        acc[r][j] = fmaf(a4.w, b4[j].w, acc[r][j]);
                    }
                }
            }
        }
        __syncthreads();
    }

    // ---- epilogue ----
    if (warp < 4) {
        #pragma unroll
        for (int im = 0; im < 2; im++) {
            #pragma unroll
            for (int jn = 0; jn < 4; jn++) {
                #pragma unroll
                for (int p = 0; p < 4; p++) {
                    int row = bm + im * 16 + g + (p >> 1) * 8;
                    int col = bn + wn + jn * 8 + t4 * 2 + (p & 1);
                    emit_out(c[im][jn][p], row, col, N, bias, res, act, Cf, Ch, Cl, Caf);
                }
            }
        }
    } else {
        #pragma unroll
        for (int r = 0; r < 12; r++) {
            int row = bm + 32 + lr0 + r;
            #pragma unroll
            for (int j = 0; j < 4; j++)
                emit_out(acc[r][j], row, bn + lane + 32 * j, N,
                         bias, res, act, Cf, Ch, Cl, Caf);
        }
    }
}

// =====================================================================
// causal attention -> fp16 hi/lo planes + fp32 copy
// =====================================================================
__global__ void attn_kernel(const float* __restrict__ qkv,
                            __half* __restrict__ yh, __half* __restrict__ yl,
                            float* __restrict__ yf) {
    int q = blockIdx.x;
    int h = blockIdx.y;
    int b = blockIdx.z;
    int tid = threadIdx.x;

    __shared__ float qs[ND];
    __shared__ float sc[NT];
    __shared__ float red[32];
    __shared__ float yp[2][ND];

    const size_t rs = 3 * NC;
    const float* qptr = qkv + ((size_t)(b * NT + q)) * rs + h * ND;
    if (tid < ND) qs[tid] = qptr[tid];
    __syncthreads();

    const float scale = 0.125f;
    int nk = q + 1;
    const float* kbase = qkv + ((size_t)b * NT) * rs + NC + h * ND;
    for (int k = tid; k < nk; k += blockDim.x) {
        const float* kp = kbase + (size_t)k * rs;
        float d = 0.f;
        #pragma unroll
        for (int i = 0; i < ND; i++) d = fmaf(qs[i], kp[i], d);
        sc[k] = d * scale;
    }
    __syncthreads();

    float m = -1e30f;
    for (int k = tid; k < nk; k += blockDim.x) m = fmaxf(m, sc[k]);
    #pragma unroll
    for (int o = 16; o; o >>= 1) m = fmaxf(m, __shfl_xor_sync(0xffffffffu, m, o));
    if ((tid & 31) == 0) red[tid >> 5] = m;
    __syncthreads();
    if (tid < 32) {
        float v = (tid < (int)(blockDim.x >> 5)) ? red[tid] : -1e30f;
        #pragma unroll
        for (int o = 16; o; o >>= 1) v = fmaxf(v, __shfl_xor_sync(0xffffffffu, v, o));
        if (tid == 0) red[0] = v;
    }
    __syncthreads();
    m = red[0];
    __syncthreads();

    float s = 0.f;
    for (int k = tid; k < nk; k += blockDim.x) {
        float e = __expf(sc[k] - m);
        sc[k] = e;
        s += e;
    }
    #pragma unroll
    for (int o = 16; o; o >>= 1) s += __shfl_xor_sync(0xffffffffu, s, o);
    if ((tid & 31) == 0) red[tid >> 5] = s;
    __syncthreads();
    if (tid < 32) {
        float v = (tid < (int)(blockDim.x >> 5)) ? red[tid] : 0.f;
        #pragma unroll
        for (int o = 16; o; o >>= 1) v += __shfl_xor_sync(0xffffffffu, v, o);
        if (tid == 0) red[0] = v;
    }
    __syncthreads();
    float inv = 1.0f / red[0];

    int part = tid >> 6, d = tid & 63;
    const float* vbase = qkv + ((size_t)b * NT) * rs + 2 * NC + h * ND;
    float acc = 0.f;
    for (int k = part; k < nk; k += 2)
        acc = fmaf(sc[k], vbase[(size_t)k * rs + d], acc);
    yp[part][d] = acc;
    __syncthreads();
    if (tid < ND) {
        float v = (yp[0][tid] + yp[1][tid]) * inv;
        __half hh, lo;
        split_h(v, hh, lo);
        size_t o = ((size_t)(b * NT + q)) * NC + h * ND + tid;
        yh[o] = hh;
        yl[o] = lo;
        yf[o] = v;
    }
}

// =====================================================================
// launch
// =====================================================================
extern "C" void kernel_launch(void* const* d_in, const int* in_sizes, int n_in,
                              void* d_out, int out_size) {
    const int*   idx    = (const int*)d_in[0];
    const float* wte    = (const float*)d_in[1];
    const float* wpe    = (const float*)d_in[2];
    const float* ln1_w  = (const float*)d_in[3];
    const float* ln1_b  = (const float*)d_in[4];
    const float* ln2_w  = (const float*)d_in[5];
    const float* ln2_b  = (const float*)d_in[6];
    const float* attn_w = (const float*)d_in[7];
    const float* attn_b = (const float*)d_in[8];
    const float* proj_w = (const float*)d_in[9];
    const float* proj_b = (const float*)d_in[10];
    const float* fc_w   = (const float*)d_in[11];
    const float* fc_b   = (const float*)d_in[12];
    const float* fcp_w  = (const float*)d_in[13];
    const float* fcp_b  = (const float*)d_in[14];
    const float* lnf_w  = (const float*)d_in[15];
    const float* lnf_b  = (const float*)d_in[16];
    const float* lmh    = (const float*)d_in[17];
    float* out = (float*)d_out;

    float *x, *qkv, *af, *af2;
    __half *xh, *xl, *yh, *yl;
    cudaGetSymbolAddress((void**)&x, g_x);
    cudaGetSymbolAddress((void**)&qkv, g_qkv);
    cudaGetSymbolAddress((void**)&xh, g_xh);
    cudaGetSymbolAddress((void**)&xl, g_xl);
    cudaGetSymbolAddress((void**)&yh, g_yh);
    cudaGetSymbolAddress((void**)&yl, g_yl);
    cudaGetSymbolAddress((void**)&af, g_af);
    cudaGetSymbolAddress((void**)&af2, g_af2);

    __half *wa_h, *wa_l, *wp_h, *wp_l, *wf_h, *wf_l, *wq_h, *wq_l, *lm_h, *lm_l;
    float *wa_f, *wp_f, *wf_f, *wq_f;
    cudaGetSymbolAddress((void**)&wa_h, g_wa_h);
    cudaGetSymbolAddress((void**)&wa_l, g_wa_l);
    cudaGetSymbolAddress((void**)&wp_h, g_wp_h);
    cudaGetSymbolAddress((void**)&wp_l, g_wp_l);
    cudaGetSymbolAddress((void**)&wf_h, g_wf_h);
    cudaGetSymbolAddress((void**)&wf_l, g_wf_l);
    cudaGetSymbolAddress((void**)&wq_h, g_wq_h);
    cudaGetSymbolAddress((void**)&wq_l, g_wq_l);
    cudaGetSymbolAddress((void**)&lm_h, g_lm_h);
    cudaGetSymbolAddress((void**)&lm_l, g_lm_l);
    cudaGetSymbolAddress((void**)&wa_f, g_wa_f);
    cudaGetSymbolAddress((void**)&wp_f, g_wp_f);
    cudaGetSymbolAddress((void**)&wf_f, g_wf_f);
    cudaGetSymbolAddress((void**)&wq_f, g_wq_f);

    cudaFuncSetAttribute(hyb_gemm, cudaFuncAttributeMaxDynamicSharedMemorySize,
                         GSMEM_BYTES);

    // ---- weight conversion ----
    dim3 tb(32, 8);
    transpose_split<<<dim3(2304 / 32, 768 / 32, 12), tb>>>(attn_w, wa_h, wa_l, wa_f, NC, 3 * NC);
    transpose_split<<<dim3(768 / 32, 768 / 32, 12), tb>>>(proj_w, wp_h, wp_l, wp_f, NC, NC);
    transpose_split<<<dim3(3072 / 32, 768 / 32, 12), tb>>>(fc_w, wf_h, wf_l, wf_f, NC, 4 * NC);
    transpose_split<<<dim3(768 / 32, 3072 / 32, 12), tb>>>(fcp_w, wq_h, wq_l, wq_f, 4 * NC, NC);
    split_kernel<<<(NV * NC + 255) / 256, 256>>>(lmh, lm_h, lm_l, NV * NC);

    embed_kernel<<<NTOK, 256>>>(idx, wte, wpe, x);

    for (int l = 0; l < NL; l++) {
        ln_kernel<<<NTOK, 256>>>(x, ln1_w + l * NC, ln1_b + l * NC, xh, xl, af);
        // qkv = act @ attn_w^T + attn_b
        hyb_gemm<<<dim3(32, 18), 384, GSMEM_BYTES>>>(
            xh, xl, af,
            wa_h + (size_t)l * 3 * NC * NC, wa_l + (size_t)l * 3 * NC * NC,
            wa_f + (size_t)l * 3 * NC * NC,
            attn_b + (size_t)l * 3 * NC, nullptr, qkv, nullptr, nullptr, nullptr,
            NTOK, 3 * NC, NC, 0);
        {
            dim3 grid(NT, NH, NB);
            attn_kernel<<<grid, 128>>>(qkv, xh, xl, af);
        }
        // x = x + y @ proj_w^T + proj_b
        hyb_gemm<<<dim3(32, 6), 384, GSMEM_BYTES>>>(
            xh, xl, af,
            wp_h + (size_t)l * NC * NC, wp_l + (size_t)l * NC * NC,
            wp_f + (size_t)l * NC * NC,
            proj_b + (size_t)l * NC, x, x, nullptr, nullptr, nullptr,
            NTOK, NC, NC, 0);
        ln_kernel<<<NTOK, 256>>>(x, ln2_w + l * NC, ln2_b + l * NC, xh, xl, af);
        // fc = gelu(act @ fc_w^T + fc_b) -> fp16 planes + fp32 copy
        hyb_gemm<<<dim3(32, 24), 384, GSMEM_BYTES>>>(
            xh, xl, af,
            wf_h + (size_t)l * 4 * NC * NC, wf_l + (size_t)l * 4 * NC * NC,
            wf_f + (size_t)l * 4 * NC * NC,
            fc_b + (size_t)l * 4 * NC, nullptr, nullptr, yh, yl, af2,
            NTOK, 4 * NC, NC, 1);
        // x = x + fc @ fcp_w^T + fcp_b
        hyb_gemm<<<dim3(32, 6), 384, GSMEM_BYTES>>>(
            yh, yl, af2,
            wq_h + (size_t)l * NC * 4 * NC, wq_l + (size_t)l * NC * 4 * NC,
            wq_f + (size_t)l * NC * 4 * NC,
            fcp_b + (size_t)l * NC, x, x, nullptr, nullptr, nullptr,
            NTOK, NC, 4 * NC, 0);
    }

    ln_kernel<<<NTOK, 256>>>(x, lnf_w, lnf_b, xh, xl, af);

    // logits = act @ lm_head^T (fp32 B = lmh itself)
    hyb_gemm<<<dim3(32, (NV + 127) / 128), 384, GSMEM_BYTES>>>(
        xh, xl, af, lm_h, lm_l, lmh,
        nullptr, nullptr, out, nullptr, nullptr, nullptr,
        NTOK, NV, NC, 0);
}

// round 10
// speedup vs baseline: 1.1885x; 1.1885x over previous
#include <cuda_runtime.h>
#include <cuda_fp16.h>
#include <math.h>
#include <stdint.h>

#define NL 12
#define NH 12
#define NC 768
#define NV 50257
#define NT 1024
#define NB 4
#define ND 64
#define NTOK (NB * NT)   // 4096

// ---- activation scratch ----
__device__ float g_x[NTOK * NC];
__device__ float g_qkv[NTOK * 3 * NC];
__device__ __half g_xh[NTOK * NC],     g_xl[NTOK * NC];
__device__ __half g_yh[NTOK * 4 * NC], g_yl[NTOK * 4 * NC];

// ---- pre-split fp16 weight planes, [N][K] layout ----
__device__ __half g_wa_h[12 * 2304 * 768], g_wa_l[12 * 2304 * 768];
__device__ __half g_wp_h[12 * 768 * 768],  g_wp_l[12 * 768 * 768];
__device__ __half g_wf_h[12 * 3072 * 768], g_wf_l[12 * 3072 * 768];
__device__ __half g_wq_h[12 * 768 * 3072], g_wq_l[12 * 768 * 3072];
__device__ __half g_lm_h[50257 * 768],     g_lm_l[50257 * 768];

// =====================================================================
// helpers
// =====================================================================
__device__ __forceinline__ uint32_t smem_u32(const void* p) {
    uint32_t a;
    asm("{ .reg .u64 t; cvta.to.shared.u64 t, %1; cvt.u32.u64 %0, t; }"
        : "=r"(a) : "l"(p));
    return a;
}
__device__ __forceinline__ void cpa16(uint32_t dst, const void* src) {
    asm volatile("cp.async.cg.shared.global [%0], [%1], 16;"
                 :: "r"(dst), "l"(src));
}
__device__ __forceinline__ uint32_t swz(uint32_t o) {
    return o ^ ((o >> 3) & 0x70);
}
__device__ __forceinline__ float gelu_f(float u) {
    return 0.5f * u * (1.0f + tanhf(0.7978845608028654f * (u + 0.044715f * u * u * u)));
}
__device__ __forceinline__ void split_h(float v, __half& hi, __half& lo) {
    hi = __float2half_rn(v);
    lo = __float2half_rn(v - __half2float(hi));
}
__device__ __forceinline__ void mma_f16(float* c, const unsigned* a,
                                        unsigned b0, unsigned b1) {
    asm volatile(
        "mma.sync.aligned.m16n8k16.row.col.f32.f16.f16.f32 "
        "{%0,%1,%2,%3}, {%4,%5,%6,%7}, {%8,%9}, {%0,%1,%2,%3};"
        : "+f"(c[0]), "+f"(c[1]), "+f"(c[2]), "+f"(c[3])
        : "r"(a[0]), "r"(a[1]), "r"(a[2]), "r"(a[3]), "r"(b0), "r"(b1));
}

// =====================================================================
// weight conversion
// =====================================================================
__global__ void transpose_split(const float* __restrict__ W,
                                __half* __restrict__ OH, __half* __restrict__ OL,
                                int K, int N) {
    __shared__ float t[32][33];
    int l = blockIdx.z;
    const float* Wl = W + (size_t)l * K * N;
    __half* OHl = OH + (size_t)l * K * N;
    __half* OLl = OL + (size_t)l * K * N;
    int n0 = blockIdx.x * 32, k0 = blockIdx.y * 32;
    int tx = threadIdx.x, ty = threadIdx.y;
    #pragma unroll
    for (int i = ty; i < 32; i += 8)
        t[i][tx] = Wl[(size_t)(k0 + i) * N + n0 + tx];
    __syncthreads();
    #pragma unroll
    for (int i = ty; i < 32; i += 8) {
        float v = t[tx][i];
        __half h, lo;
        split_h(v, h, lo);
        OHl[(size_t)(n0 + i) * K + k0 + tx] = h;
        OLl[(size_t)(n0 + i) * K + k0 + tx] = lo;
    }
}

__global__ void split_kernel(const float* __restrict__ W,
                             __half* __restrict__ H, __half* __restrict__ L,
                             int n) {
    int i = blockIdx.x * blockDim.x + threadIdx.x;
    if (i < n) {
        __half h, lo;
        split_h(W[i], h, lo);
        H[i] = h;
        L[i] = lo;
    }
}

// =====================================================================
// embedding
// =====================================================================
__global__ void embed_kernel(const int* __restrict__ idx,
                             const float* __restrict__ wte,
                             const float* __restrict__ wpe,
                             float* __restrict__ x) {
    int row = blockIdx.x;
    int t = row % NT;
    int tok = idx[row];
    const float* we = wte + (size_t)tok * NC;
    const float* wp = wpe + (size_t)t * NC;
    float* out = x + (size_t)row * NC;
    for (int c = threadIdx.x; c < NC; c += blockDim.x)
        out[c] = we[c] + wp[c];
}

// =====================================================================
// layernorm -> fp16 hi/lo planes
// =====================================================================
__global__ void ln_kernel(const float* __restrict__ x,
                          const float* __restrict__ w,
                          const float* __restrict__ b,
                          __half* __restrict__ oh, __half* __restrict__ ol) {
    int row = blockIdx.x;
    const float* xr = x + (size_t)row * NC;
    __shared__ float red[32];
    int tid = threadIdx.x;
    int nwarp = blockDim.x >> 5;

    float s = 0.f;
    for (int c = tid; c < NC; c += blockDim.x) s += xr[c];
    #pragma unroll
    for (int o = 16; o; o >>= 1) s += __shfl_xor_sync(0xffffffffu, s, o);
    if ((tid & 31) == 0) red[tid >> 5] = s;
    __syncthreads();
    if (tid < 32) {
        float v = (tid < nwarp) ? red[tid] : 0.f;
        #pragma unroll
        for (int o = 16; o; o >>= 1) v += __shfl_xor_sync(0xffffffffu, v, o);
        if (tid == 0) red[0] = v;
    }
    __syncthreads();
    float mu = red[0] * (1.0f / NC);
    __syncthreads();

    float s2 = 0.f;
    for (int c = tid; c < NC; c += blockDim.x) {
        float d = xr[c] - mu;
        s2 += d * d;
    }
    #pragma unroll
    for (int o = 16; o; o >>= 1) s2 += __shfl_xor_sync(0xffffffffu, s2, o);
    if ((tid & 31) == 0) red[tid >> 5] = s2;
    __syncthreads();
    if (tid < 32) {
        float v = (tid < nwarp) ? red[tid] : 0.f;
        #pragma unroll
        for (int o = 16; o; o >>= 1) v += __shfl_xor_sync(0xffffffffu, v, o);
        if (tid == 0) red[0] = v;
    }
    __syncthreads();
    float var = red[0] * (1.0f / NC);
    float rstd = rsqrtf(var + 1e-5f);
    for (int c = tid; c < NC; c += blockDim.x) {
        float v = (xr[c] - mu) * rstd * w[c] + b[c];
        __half h, lo;
        split_h(v, h, lo);
        oh[(size_t)row * NC + c] = h;
        ol[(size_t)row * NC + c] = lo;
    }
}

// =====================================================================
// GEMM (NT): C = A @ B^T, fp16 hi/lo 3-pass split, PASS-MAJOR mma order.
// CTA tile 128x128, K stages of 64, 256 threads, double-buffered smem.
// =====================================================================
#define GBM 128
#define GBN 128
#define GKC 64
#define PLANE_B 16384
#define STAGE_B (4 * PLANE_B)
#define GSMEM_BYTES (2 * STAGE_B + 1024)

__device__ __forceinline__ void stage_load(uint32_t sb,
        const __half* Ah, const __half* Al,
        const __half* Bh, const __half* Bl,
        int bm, int bn, int N, int K, int k0, int tid) {
    #pragma unroll
    for (int i = 0; i < 16; i++) {
        int id = i * 256 + tid;           // 0..4095 granules of 16B
        int p = id >> 10;
        int cid = id & 1023;
        int row = cid >> 3, c16 = cid & 7;
        uint32_t dst = sb + p * PLANE_B + swz((uint32_t)(row * 128 + c16 * 16));
        if (p < 2) {
            cpa16(dst, (p ? Al : Ah) + (size_t)(bm + row) * K + k0 + c16 * 8);
        } else {
            int gn = bn + row;
            if (gn < N)
                cpa16(dst, (p == 3 ? Bl : Bh) + (size_t)gn * K + k0 + c16 * 8);
        }
    }
}

__global__ void __launch_bounds__(256) gemm_nt(
    const __half* __restrict__ Ah, const __half* __restrict__ Al,
    const __half* __restrict__ Bh, const __half* __restrict__ Bl,
    const float* __restrict__ bias, const float* __restrict__ res,
    float* __restrict__ Cf, __half* __restrict__ Ch, __half* __restrict__ Cl,
    int M, int N, int K, int act)
{
    extern __shared__ char dsm[];
    uint32_t sb0 = (smem_u32(dsm) + 1023) & ~1023u;
    const char* sm0 = dsm + (sb0 - smem_u32(dsm));

    int tid = threadIdx.x;
    int lane = tid & 31, warp = tid >> 5;
    int g = lane >> 2, t4 = lane & 3;
    int wm = (warp & 1) * 64;          // 2 m-warps x 4 n-warps
    int wn = (warp >> 1) * 32;
    int bm = blockIdx.x * GBM;
    int bn = blockIdx.y * GBN;
    const int S = K / GKC;

    float c[4][4][4] = {};

    stage_load(sb0, Ah, Al, Bh, Bl, bm, bn, N, K, 0, tid);
    asm volatile("cp.async.commit_group;");

    for (int s = 0; s < S; s++) {
        if (s + 1 < S) {
            stage_load(sb0 + ((s + 1) & 1) * STAGE_B, Ah, Al, Bh, Bl,
                       bm, bn, N, K, (s + 1) * GKC, tid);
            asm volatile("cp.async.commit_group;");
            asm volatile("cp.async.wait_group 1;");
        } else {
            asm volatile("cp.async.wait_group 0;");
        }
        __syncthreads();

        const char* st = sm0 + (s & 1) * STAGE_B;
        #pragma unroll
        for (int kk = 0; kk < 4; kk++) {
            int kw = kk * 8;
            unsigned ah[4][4], al[4][4], bhf[4][2], blf[4][2];
            #pragma unroll
            for (int im = 0; im < 4; im++) {
                int r0 = wm + im * 16 + g, r8 = r0 + 8;
                ah[im][0] = *(const unsigned*)(st + swz(r0 * 128 + (kw + t4) * 4));
                ah[im][1] = *(const unsigned*)(st + swz(r8 * 128 + (kw + t4) * 4));
                ah[im][2] = *(const unsigned*)(st + swz(r0 * 128 + (kw + 4 + t4) * 4));
                ah[im][3] = *(const unsigned*)(st + swz(r8 * 128 + (kw + 4 + t4) * 4));
                al[im][0] = *(const unsigned*)(st + PLANE_B + swz(r0 * 128 + (kw + t4) * 4));
                al[im][1] = *(const unsigned*)(st + PLANE_B + swz(r8 * 128 + (kw + t4) * 4));
                al[im][2] = *(const unsigned*)(st + PLANE_B + swz(r0 * 128 + (kw + 4 + t4) * 4));
                al[im][3] = *(const unsigned*)(st + PLANE_B + swz(r8 * 128 + (kw + 4 + t4) * 4));
            }
            #pragma unroll
            for (int jn = 0; jn < 4; jn++) {
                int n = wn + jn * 8 + g;
                bhf[jn][0] = *(const unsigned*)(st + 2 * PLANE_B + swz(n * 128 + (kw + t4) * 4));
                bhf[jn][1] = *(const unsigned*)(st + 2 * PLANE_B + swz(n * 128 + (kw + 4 + t4) * 4));
                blf[jn][0] = *(const unsigned*)(st + 3 * PLANE_B + swz(n * 128 + (kw + t4) * 4));
                blf[jn][1] = *(const unsigned*)(st + 3 * PLANE_B + swz(n * 128 + (kw + 4 + t4) * 4));
            }
            // pass-major: consecutive mmas never share an accumulator
            #pragma unroll
            for (int jn = 0; jn < 4; jn++)
                #pragma unroll
                for (int im = 0; im < 4; im++)
                    mma_f16(c[im][jn], ah[im], bhf[jn][0], bhf[jn][1]);
            #pragma unroll
            for (int jn = 0; jn < 4; jn++)
                #pragma unroll
                for (int im = 0; im < 4; im++)
                    mma_f16(c[im][jn], ah[im], blf[jn][0], blf[jn][1]);
            #pragma unroll
            for (int jn = 0; jn < 4; jn++)
                #pragma unroll
                for (int im = 0; im < 4; im++)
                    mma_f16(c[im][jn], al[im], bhf[jn][0], bhf[jn][1]);
        }
        __syncthreads();
    }

    #pragma unroll
    for (int im = 0; im < 4; im++) {
        #pragma unroll
        for (int jn = 0; jn < 4; jn++) {
            #pragma unroll
            for (int p = 0; p < 4; p++) {
                int row = bm + wm + im * 16 + g + (p >> 1) * 8;
                int col = bn + wn + jn * 8 + t4 * 2 + (p & 1);
                if (col < N) {
                    float v = c[im][jn][p];
                    if (bias) v += bias[col];
                    if (act) v = gelu_f(v);
                    if (Ch) {
                        __half h, lo;
                        split_h(v, h, lo);
                        Ch[(size_t)row * N + col] = h;
                        Cl[(size_t)row * N + col] = lo;
                    } else {
                        if (res) v += res[(size_t)row * N + col];
                        Cf[(size_t)row * N + col] = v;
                    }
                }
            }
        }
    }
}

// =====================================================================
// causal attention -> fp16 hi/lo planes
// =====================================================================
__global__ void attn_kernel(const float* __restrict__ qkv,
                            __half* __restrict__ yh, __half* __restrict__ yl) {
    int q = blockIdx.x;
    int h = blockIdx.y;
    int b = blockIdx.z;
    int tid = threadIdx.x;

    __shared__ float qs[ND];
    __shared__ float sc[NT];
    __shared__ float red[32];
    __shared__ float yp[2][ND];

    const size_t rs = 3 * NC;
    const float* qptr = qkv + ((size_t)(b * NT + q)) * rs + h * ND;
    if (tid < ND) qs[tid] = qptr[tid];
    __syncthreads();

    const float scale = 0.125f;
    int nk = q + 1;
    const float* kbase = qkv + ((size_t)b * NT) * rs + NC + h * ND;
    for (int k = tid; k < nk; k += blockDim.x) {
        const float* kp = kbase + (size_t)k * rs;
        float d = 0.f;
        #pragma unroll
        for (int i = 0; i < ND; i++) d = fmaf(qs[i], kp[i], d);
        sc[k] = d * scale;
    }
    __syncthreads();

    float m = -1e30f;
    for (int k = tid; k < nk; k += blockDim.x) m = fmaxf(m, sc[k]);
    #pragma unroll
    for (int o = 16; o; o >>= 1) m = fmaxf(m, __shfl_xor_sync(0xffffffffu, m, o));
    if ((tid & 31) == 0) red[tid >> 5] = m;
    __syncthreads();
    if (tid < 32) {
        float v = (tid < (int)(blockDim.x >> 5)) ? red[tid] : -1e30f;
        #pragma unroll
        for (int o = 16; o; o >>= 1) v = fmaxf(v, __shfl_xor_sync(0xffffffffu, v, o));
        if (tid == 0) red[0] = v;
    }
    __syncthreads();
    m = red[0];
    __syncthreads();

    float s = 0.f;
    for (int k = tid; k < nk; k += blockDim.x) {
        float e = __expf(sc[k] - m);
        sc[k] = e;
        s += e;
    }
    #pragma unroll
    for (int o = 16; o; o >>= 1) s += __shfl_xor_sync(0xffffffffu, s, o);
    if ((tid & 31) == 0) red[tid >> 5] = s;
    __syncthreads();
    if (tid < 32) {
        float v = (tid < (int)(blockDim.x >> 5)) ? red[tid] : 0.f;
        #pragma unroll
        for (int o = 16; o; o >>= 1) v += __shfl_xor_sync(0xffffffffu, v, o);
        if (tid == 0) red[0] = v;
    }
    __syncthreads();
    float inv = 1.0f / red[0];

    int part = tid >> 6, d = tid & 63;
    const float* vbase = qkv + ((size_t)b * NT) * rs + 2 * NC + h * ND;
    float acc = 0.f;
    for (int k = part; k < nk; k += 2)
        acc = fmaf(sc[k], vbase[(size_t)k * rs + d], acc);
    yp[part][d] = acc;
    __syncthreads();
    if (tid < ND) {
        float v = (yp[0][tid] + yp[1][tid]) * inv;
        __half hh, lo;
        split_h(v, hh, lo);
        size_t o = ((size_t)(b * NT + q)) * NC + h * ND + tid;
        yh[o] = hh;
        yl[o] = lo;
    }
}

// =====================================================================
// launch
// =====================================================================
extern "C" void kernel_launch(void* const* d_in, const int* in_sizes, int n_in,
                              void* d_out, int out_size) {
    const int*   idx    = (const int*)d_in[0];
    const float* wte    = (const float*)d_in[1];
    const float* wpe    = (const float*)d_in[2];
    const float* ln1_w  = (const float*)d_in[3];
    const float* ln1_b  = (const float*)d_in[4];
    const float* ln2_w  = (const float*)d_in[5];
    const float* ln2_b  = (const float*)d_in[6];
    const float* attn_w = (const float*)d_in[7];
    const float* attn_b = (const float*)d_in[8];
    const float* proj_w = (const float*)d_in[9];
    const float* proj_b = (const float*)d_in[10];
    const float* fc_w   = (const float*)d_in[11];
    const float* fc_b   = (const float*)d_in[12];
    const float* fcp_w  = (const float*)d_in[13];
    const float* fcp_b  = (const float*)d_in[14];
    const float* lnf_w  = (const float*)d_in[15];
    const float* lnf_b  = (const float*)d_in[16];
    const float* lmh    = (const float*)d_in[17];
    float* out = (float*)d_out;

    float *x, *qkv;
    __half *xh, *xl, *yh, *yl;
    cudaGetSymbolAddress((void**)&x, g_x);
    cudaGetSymbolAddress((void**)&qkv, g_qkv);
    cudaGetSymbolAddress((void**)&xh, g_xh);
    cudaGetSymbolAddress((void**)&xl, g_xl);
    cudaGetSymbolAddress((void**)&yh, g_yh);
    cudaGetSymbolAddress((void**)&yl, g_yl);

    __half *wa_h, *wa_l, *wp_h, *wp_l, *wf_h, *wf_l, *wq_h, *wq_l, *lm_h, *lm_l;
    cudaGetSymbolAddress((void**)&wa_h, g_wa_h);
    cudaGetSymbolAddress((void**)&wa_l, g_wa_l);
    cudaGetSymbolAddress((void**)&wp_h, g_wp_h);
    cudaGetSymbolAddress((void**)&wp_l, g_wp_l);
    cudaGetSymbolAddress((void**)&wf_h, g_wf_h);
    cudaGetSymbolAddress((void**)&wf_l, g_wf_l);
    cudaGetSymbolAddress((void**)&wq_h, g_wq_h);
    cudaGetSymbolAddress((void**)&wq_l, g_wq_l);
    cudaGetSymbolAddress((void**)&lm_h, g_lm_h);
    cudaGetSymbolAddress((void**)&lm_l, g_lm_l);

    cudaFuncSetAttribute(gemm_nt, cudaFuncAttributeMaxDynamicSharedMemorySize,
                         GSMEM_BYTES);

    dim3 tb(32, 8);
    transpose_split<<<dim3(2304 / 32, 768 / 32, 12), tb>>>(attn_w, wa_h, wa_l, NC, 3 * NC);
    transpose_split<<<dim3(768 / 32, 768 / 32, 12), tb>>>(proj_w, wp_h, wp_l, NC, NC);
    transpose_split<<<dim3(3072 / 32, 768 / 32, 12), tb>>>(fc_w, wf_h, wf_l, NC, 4 * NC);
    transpose_split<<<dim3(768 / 32, 3072 / 32, 12), tb>>>(fcp_w, wq_h, wq_l, 4 * NC, NC);
    split_kernel<<<(NV * NC + 255) / 256, 256>>>(lmh, lm_h, lm_l, NV * NC);

    embed_kernel<<<NTOK, 256>>>(idx, wte, wpe, x);

    for (int l = 0; l < NL; l++) {
        ln_kernel<<<NTOK, 256>>>(x, ln1_w + l * NC, ln1_b + l * NC, xh, xl);
        gemm_nt<<<dim3(NTOK / GBM, (3 * NC) / GBN), 256, GSMEM_BYTES>>>(
            xh, xl, wa_h + (size_t)l * 3 * NC * NC, wa_l + (size_t)l * 3 * NC * NC,
            attn_b + (size_t)l * 3 * NC, nullptr, qkv, nullptr, nullptr,
            NTOK, 3 * NC, NC, 0);
        {
            dim3 grid(NT, NH, NB);
            attn_kernel<<<grid, 128>>>(qkv, xh, xl);
        }
        gemm_nt<<<dim3(NTOK / GBM, NC / GBN), 256, GSMEM_BYTES>>>(
            xh, xl, wp_h + (size_t)l * NC * NC, wp_l + (size_t)l * NC * NC,
            proj_b + (size_t)l * NC, x, x, nullptr, nullptr,
            NTOK, NC, NC, 0);
        ln_kernel<<<NTOK, 256>>>(x, ln2_w + l * NC, ln2_b + l * NC, xh, xl);
        gemm_nt<<<dim3(NTOK / GBM, (4 * NC) / GBN), 256, GSMEM_BYTES>>>(
            xh, xl, wf_h + (size_t)l * 4 * NC * NC, wf_l + (size_t)l * 4 * NC * NC,
            fc_b + (size_t)l * 4 * NC, nullptr, nullptr, yh, yl,
            NTOK, 4 * NC, NC, 1);
        gemm_nt<<<dim3(NTOK / GBM, NC / GBN), 256, GSMEM_BYTES>>>(
            yh, yl, wq_h + (size_t)l * NC * 4 * NC, wq_l + (size_t)l * NC * 4 * NC,
            fcp_b + (size_t)l * NC, x, x, nullptr, nullptr,
            NTOK, NC, 4 * NC, 0);
    }

    ln_kernel<<<NTOK, 256>>>(x, lnf_w, lnf_b, xh, xl);

    gemm_nt<<<dim3(NTOK / GBM, (NV + GBN - 1) / GBN), 256, GSMEM_BYTES>>>(
        xh, xl, lm_h, lm_l, nullptr, nullptr, out, nullptr, nullptr,
        NTOK, NV, NC, 0);
}

// round 11
// speedup vs baseline: 1.2083x; 1.0167x over previous
#include <cuda_runtime.h>
#include <cuda_fp16.h>
#include <math.h>
#include <stdint.h>

#define NL 12
#define NH 12
#define NC 768
#define NV 50257
#define NT 1024
#define NB 4
#define ND 64
#define NTOK (NB * NT)   // 4096

// ---- activation scratch ----
__device__ float g_x[NTOK * NC];
__device__ float g_qkv[NTOK * 3 * NC];
__device__ __half g_xh[NTOK * NC],     g_xl[NTOK * NC];
__device__ __half g_yh[NTOK * 4 * NC], g_yl[NTOK * 4 * NC];

// ---- pre-split fp16 weight planes, [N][K] layout ----
__device__ __half g_wa_h[12 * 2304 * 768], g_wa_l[12 * 2304 * 768];
__device__ __half g_wp_h[12 * 768 * 768],  g_wp_l[12 * 768 * 768];
__device__ __half g_wf_h[12 * 3072 * 768], g_wf_l[12 * 3072 * 768];
__device__ __half g_wq_h[12 * 768 * 3072], g_wq_l[12 * 768 * 3072];
__device__ __half g_lm_h[50257 * 768],     g_lm_l[50257 * 768];

// =====================================================================
// helpers
// =====================================================================
__device__ __forceinline__ uint32_t smem_u32(const void* p) {
    uint32_t a;
    asm("{ .reg .u64 t; cvta.to.shared.u64 t, %1; cvt.u32.u64 %0, t; }"
        : "=r"(a) : "l"(p));
    return a;
}
__device__ __forceinline__ void cpa16(uint32_t dst, const void* src) {
    asm volatile("cp.async.cg.shared.global [%0], [%1], 16;"
                 :: "r"(dst), "l"(src));
}
__device__ __forceinline__ uint32_t swz(uint32_t o) {
    return o ^ ((o >> 3) & 0x70);
}
__device__ __forceinline__ float gelu_f(float u) {
    return 0.5f * u * (1.0f + tanhf(0.7978845608028654f * (u + 0.044715f * u * u * u)));
}
__device__ __forceinline__ void split_h(float v, __half& hi, __half& lo) {
    hi = __float2half_rn(v);
    lo = __float2half_rn(v - __half2float(hi));
}
__device__ __forceinline__ void mma_f16(float* c, const unsigned* a,
                                        unsigned b0, unsigned b1) {
    asm volatile(
        "mma.sync.aligned.m16n8k16.row.col.f32.f16.f16.f32 "
        "{%0,%1,%2,%3}, {%4,%5,%6,%7}, {%8,%9}, {%0,%1,%2,%3};"
        : "+f"(c[0]), "+f"(c[1]), "+f"(c[2]), "+f"(c[3])
        : "r"(a[0]), "r"(a[1]), "r"(a[2]), "r"(a[3]), "r"(b0), "r"(b1));
}

// =====================================================================
// weight conversion
// =====================================================================
__global__ void transpose_split(const float* __restrict__ W,
                                __half* __restrict__ OH, __half* __restrict__ OL,
                                int K, int N) {
    __shared__ float t[32][33];
    int l = blockIdx.z;
    const float* Wl = W + (size_t)l * K * N;
    __half* OHl = OH + (size_t)l * K * N;
    __half* OLl = OL + (size_t)l * K * N;
    int n0 = blockIdx.x * 32, k0 = blockIdx.y * 32;
    int tx = threadIdx.x, ty = threadIdx.y;
    #pragma unroll
    for (int i = ty; i < 32; i += 8)
        t[i][tx] = Wl[(size_t)(k0 + i) * N + n0 + tx];
    __syncthreads();
    #pragma unroll
    for (int i = ty; i < 32; i += 8) {
        float v = t[tx][i];
        __half h, lo;
        split_h(v, h, lo);
        OHl[(size_t)(n0 + i) * K + k0 + tx] = h;
        OLl[(size_t)(n0 + i) * K + k0 + tx] = lo;
    }
}

__global__ void split_kernel(const float* __restrict__ W,
                             __half* __restrict__ H, __half* __restrict__ L,
                             int n) {
    int i = blockIdx.x * blockDim.x + threadIdx.x;
    if (i < n) {
        __half h, lo;
        split_h(W[i], h, lo);
        H[i] = h;
        L[i] = lo;
    }
}

// =====================================================================
// embedding
// =====================================================================
__global__ void embed_kernel(const int* __restrict__ idx,
                             const float* __restrict__ wte,
                             const float* __restrict__ wpe,
                             float* __restrict__ x) {
    int row = blockIdx.x;
    int t = row % NT;
    int tok = idx[row];
    const float* we = wte + (size_t)tok * NC;
    const float* wp = wpe + (size_t)t * NC;
    float* out = x + (size_t)row * NC;
    for (int c = threadIdx.x; c < NC; c += blockDim.x)
        out[c] = we[c] + wp[c];
}

// =====================================================================
// layernorm -> fp16 hi/lo planes
// =====================================================================
__global__ void ln_kernel(const float* __restrict__ x,
                          const float* __restrict__ w,
                          const float* __restrict__ b,
                          __half* __restrict__ oh, __half* __restrict__ ol) {
    int row = blockIdx.x;
    const float* xr = x + (size_t)row * NC;
    __shared__ float red[32];
    int tid = threadIdx.x;
    int nwarp = blockDim.x >> 5;

    float s = 0.f;
    for (int c = tid; c < NC; c += blockDim.x) s += xr[c];
    #pragma unroll
    for (int o = 16; o; o >>= 1) s += __shfl_xor_sync(0xffffffffu, s, o);
    if ((tid & 31) == 0) red[tid >> 5] = s;
    __syncthreads();
    if (tid < 32) {
        float v = (tid < nwarp) ? red[tid] : 0.f;
        #pragma unroll
        for (int o = 16; o; o >>= 1) v += __shfl_xor_sync(0xffffffffu, v, o);
        if (tid == 0) red[0] = v;
    }
    __syncthreads();
    float mu = red[0] * (1.0f / NC);
    __syncthreads();

    float s2 = 0.f;
    for (int c = tid; c < NC; c += blockDim.x) {
        float d = xr[c] - mu;
        s2 += d * d;
    }
    #pragma unroll
    for (int o = 16; o; o >>= 1) s2 += __shfl_xor_sync(0xffffffffu, s2, o);
    if ((tid & 31) == 0) red[tid >> 5] = s2;
    __syncthreads();
    if (tid < 32) {
        float v = (tid < nwarp) ? red[tid] : 0.f;
        #pragma unroll
        for (int o = 16; o; o >>= 1) v += __shfl_xor_sync(0xffffffffu, v, o);
        if (tid == 0) red[0] = v;
    }
    __syncthreads();
    float var = red[0] * (1.0f / NC);
    float rstd = rsqrtf(var + 1e-5f);
    for (int c = tid; c < NC; c += blockDim.x) {
        float v = (xr[c] - mu) * rstd * w[c] + b[c];
        __half h, lo;
        split_h(v, h, lo);
        oh[(size_t)row * NC + c] = h;
        ol[(size_t)row * NC + c] = lo;
    }
}

// =====================================================================
// GEMM (NT): C = A @ B^T, fp16 hi/lo split (2 or 3 passes), pass-major.
// CTA tile 128x64, K stages of 64, 256 threads, double-buffered smem,
// 2 CTAs/SM (16 resident warps -> tests HMMA warp-feed scaling).
// =====================================================================
#define GBM 128
#define GBN 64
#define GKC 64
#define OAH 0
#define OAL 16384
#define OBH 32768
#define OBL 40960
#define STAGE_B 49152
#define GSMEM_BYTES (2 * STAGE_B + 1024)

__device__ __forceinline__ void stage_load(uint32_t sb,
        const __half* Ah, const __half* Al,
        const __half* Bh, const __half* Bl,
        int bm, int bn, int N, int K, int k0, int tid) {
    #pragma unroll
    for (int i = 0; i < 12; i++) {
        int id = i * 256 + tid;                // 0..3071 granules of 16B
        if (id < 2048) {                       // A planes, 128 rows
            int p = id >> 10;
            int cid = id & 1023;
            int row = cid >> 3, c16 = cid & 7;
            cpa16(sb + (p ? OAL : OAH) + swz((uint32_t)(row * 128 + c16 * 16)),
                  (p ? Al : Ah) + (size_t)(bm + row) * K + k0 + c16 * 8);
        } else {                               // B planes, 64 rows
            int t = id - 2048;
            int p = t >> 9;
            int cid = t & 511;
            int row = cid >> 3, c16 = cid & 7;
            int gn = bn + row;
            if (gn < N)
                cpa16(sb + (p ? OBL : OBH) + swz((uint32_t)(row * 128 + c16 * 16)),
                      (p ? Bl : Bh) + (size_t)gn * K + k0 + c16 * 8);
        }
    }
}

__global__ void __launch_bounds__(256, 2) gemm_nt(
    const __half* __restrict__ Ah, const __half* __restrict__ Al,
    const __half* __restrict__ Bh, const __half* __restrict__ Bl,
    const float* __restrict__ bias, const float* __restrict__ res,
    float* __restrict__ Cf, __half* __restrict__ Ch, __half* __restrict__ Cl,
    int M, int N, int K, int act, int npass)
{
    extern __shared__ char dsm[];
    uint32_t sb0 = (smem_u32(dsm) + 1023) & ~1023u;
    const char* sm0 = dsm + (sb0 - smem_u32(dsm));

    int tid = threadIdx.x;
    int lane = tid & 31, warp = tid >> 5;
    int g = lane >> 2, t4 = lane & 3;
    int wm = (warp & 3) * 32;          // 4 m-warps x 2 n-warps -> 32x32 warp tile
    int wn = (warp >> 2) * 32;
    int bm = blockIdx.x * GBM;
    int bn = blockIdx.y * GBN;
    const int S = K / GKC;

    float c[2][4][4] = {};

    stage_load(sb0, Ah, Al, Bh, Bl, bm, bn, N, K, 0, tid);
    asm volatile("cp.async.commit_group;");

    for (int s = 0; s < S; s++) {
        if (s + 1 < S) {
            stage_load(sb0 + ((s + 1) & 1) * STAGE_B, Ah, Al, Bh, Bl,
                       bm, bn, N, K, (s + 1) * GKC, tid);
            asm volatile("cp.async.commit_group;");
            asm volatile("cp.async.wait_group 1;");
        } else {
            asm volatile("cp.async.wait_group 0;");
        }
        __syncthreads();

        const char* st = sm0 + (s & 1) * STAGE_B;
        #pragma unroll
        for (int kk = 0; kk < 4; kk++) {
            int kw = kk * 8;
            unsigned ah[2][4], al[2][4], bhf[4][2], blf[4][2];
            #pragma unroll
            for (int im = 0; im < 2; im++) {
                int r0 = wm + im * 16 + g, r8 = r0 + 8;
                ah[im][0] = *(const unsigned*)(st + OAH + swz(r0 * 128 + (kw + t4) * 4));
                ah[im][1] = *(const unsigned*)(st + OAH + swz(r8 * 128 + (kw + t4) * 4));
                ah[im][2] = *(const unsigned*)(st + OAH + swz(r0 * 128 + (kw + 4 + t4) * 4));
                ah[im][3] = *(const unsigned*)(st + OAH + swz(r8 * 128 + (kw + 4 + t4) * 4));
                al[im][0] = *(const unsigned*)(st + OAL + swz(r0 * 128 + (kw + t4) * 4));
                al[im][1] = *(const unsigned*)(st + OAL + swz(r8 * 128 + (kw + t4) * 4));
                al[im][2] = *(const unsigned*)(st + OAL + swz(r0 * 128 + (kw + 4 + t4) * 4));
                al[im][3] = *(const unsigned*)(st + OAL + swz(r8 * 128 + (kw + 4 + t4) * 4));
            }
            #pragma unroll
            for (int jn = 0; jn < 4; jn++) {
                int n = wn + jn * 8 + g;
                bhf[jn][0] = *(const unsigned*)(st + OBH + swz(n * 128 + (kw + t4) * 4));
                bhf[jn][1] = *(const unsigned*)(st + OBH + swz(n * 128 + (kw + 4 + t4) * 4));
                blf[jn][0] = *(const unsigned*)(st + OBL + swz(n * 128 + (kw + t4) * 4));
                blf[jn][1] = *(const unsigned*)(st + OBL + swz(n * 128 + (kw + 4 + t4) * 4));
            }
            // pass-major issue order
            #pragma unroll
            for (int jn = 0; jn < 4; jn++)
                #pragma unroll
                for (int im = 0; im < 2; im++)
                    mma_f16(c[im][jn], ah[im], bhf[jn][0], bhf[jn][1]);
            #pragma unroll
            for (int jn = 0; jn < 4; jn++)
                #pragma unroll
                for (int im = 0; im < 2; im++)
                    mma_f16(c[im][jn], ah[im], blf[jn][0], blf[jn][1]);
            if (npass == 3) {
                #pragma unroll
                for (int jn = 0; jn < 4; jn++)
                    #pragma unroll
                    for (int im = 0; im < 2; im++)
                        mma_f16(c[im][jn], al[im], bhf[jn][0], bhf[jn][1]);
            }
        }
        __syncthreads();
    }

    #pragma unroll
    for (int im = 0; im < 2; im++) {
        #pragma unroll
        for (int jn = 0; jn < 4; jn++) {
            #pragma unroll
            for (int p = 0; p < 4; p++) {
                int row = bm + wm + im * 16 + g + (p >> 1) * 8;
                int col = bn + wn + jn * 8 + t4 * 2 + (p & 1);
                if (col < N) {
                    float v = c[im][jn][p];
                    if (bias) v += bias[col];
                    if (act) v = gelu_f(v);
                    if (Ch) {
                        __half h, lo;
                        split_h(v, h, lo);
                        Ch[(size_t)row * N + col] = h;
                        Cl[(size_t)row * N + col] = lo;
                    } else {
                        if (res) v += res[(size_t)row * N + col];
                        Cf[(size_t)row * N + col] = v;
                    }
                }
            }
        }
    }
}

// =====================================================================
// causal attention -> fp16 hi/lo planes
// =====================================================================
__global__ void attn_kernel(const float* __restrict__ qkv,
                            __half* __restrict__ yh, __half* __restrict__ yl) {
    int q = blockIdx.x;
    int h = blockIdx.y;
    int b = blockIdx.z;
    int tid = threadIdx.x;

    __shared__ float qs[ND];
    __shared__ float sc[NT];
    __shared__ float red[32];
    __shared__ float yp[2][ND];

    const size_t rs = 3 * NC;
    const float* qptr = qkv + ((size_t)(b * NT + q)) * rs + h * ND;
    if (tid < ND) qs[tid] = qptr[tid];
    __syncthreads();

    const float scale = 0.125f;
    int nk = q + 1;
    const float* kbase = qkv + ((size_t)b * NT) * rs + NC + h * ND;
    for (int k = tid; k < nk; k += blockDim.x) {
        const float* kp = kbase + (size_t)k * rs;
        float d = 0.f;
        #pragma unroll
        for (int i = 0; i < ND; i++) d = fmaf(qs[i], kp[i], d);
        sc[k] = d * scale;
    }
    __syncthreads();

    float m = -1e30f;
    for (int k = tid; k < nk; k += blockDim.x) m = fmaxf(m, sc[k]);
    #pragma unroll
    for (int o = 16; o; o >>= 1) m = fmaxf(m, __shfl_xor_sync(0xffffffffu, m, o));
    if ((tid & 31) == 0) red[tid >> 5] = m;
    __syncthreads();
    if (tid < 32) {
        float v = (tid < (int)(blockDim.x >> 5)) ? red[tid] : -1e30f;
        #pragma unroll
        for (int o = 16; o; o >>= 1) v = fmaxf(v, __shfl_xor_sync(0xffffffffu, v, o));
        if (tid == 0) red[0] = v;
    }
    __syncthreads();
    m = red[0];
    __syncthreads();

    float s = 0.f;
    for (int k = tid; k < nk; k += blockDim.x) {
        float e = __expf(sc[k] - m);
        sc[k] = e;
        s += e;
    }
    #pragma unroll
    for (int o = 16; o; o >>= 1) s += __shfl_xor_sync(0xffffffffu, s, o);
    if ((tid & 31) == 0) red[tid >> 5] = s;
    __syncthreads();
    if (tid < 32) {
        float v = (tid < (int)(blockDim.x >> 5)) ? red[tid] : 0.f;
        #pragma unroll
        for (int o = 16; o; o >>= 1) v += __shfl_xor_sync(0xffffffffu, v, o);
        if (tid == 0) red[0] = v;
    }
    __syncthreads();
    float inv = 1.0f / red[0];

    int part = tid >> 6, d = tid & 63;
    const float* vbase = qkv + ((size_t)b * NT) * rs + 2 * NC + h * ND;
    float acc = 0.f;
    for (int k = part; k < nk; k += 2)
        acc = fmaf(sc[k], vbase[(size_t)k * rs + d], acc);
    yp[part][d] = acc;
    __syncthreads();
    if (tid < ND) {
        float v = (yp[0][tid] + yp[1][tid]) * inv;
        __half hh, lo;
        split_h(v, hh, lo);
        size_t o = ((size_t)(b * NT + q)) * NC + h * ND + tid;
        yh[o] = hh;
        yl[o] = lo;
    }
}

// =====================================================================
// launch
// =====================================================================
extern "C" void kernel_launch(void* const* d_in, const int* in_sizes, int n_in,
                              void* d_out, int out_size) {
    const int*   idx    = (const int*)d_in[0];
    const float* wte    = (const float*)d_in[1];
    const float* wpe    = (const float*)d_in[2];
    const float* ln1_w  = (const float*)d_in[3];
    const float* ln1_b  = (const float*)d_in[4];
    const float* ln2_w  = (const float*)d_in[5];
    const float* ln2_b  = (const float*)d_in[6];
    const float* attn_w = (const float*)d_in[7];
    const float* attn_b = (const float*)d_in[8];
    const float* proj_w = (const float*)d_in[9];
    const float* proj_b = (const float*)d_in[10];
    const float* fc_w   = (const float*)d_in[11];
    const float* fc_b   = (const float*)d_in[12];
    const float* fcp_w  = (const float*)d_in[13];
    const float* fcp_b  = (const float*)d_in[14];
    const float* lnf_w  = (const float*)d_in[15];
    const float* lnf_b  = (const float*)d_in[16];
    const float* lmh    = (const float*)d_in[17];
    float* out = (float*)d_out;

    float *x, *qkv;
    __half *xh, *xl, *yh, *yl;
    cudaGetSymbolAddress((void**)&x, g_x);
    cudaGetSymbolAddress((void**)&qkv, g_qkv);
    cudaGetSymbolAddress((void**)&xh, g_xh);
    cudaGetSymbolAddress((void**)&xl, g_xl);
    cudaGetSymbolAddress((void**)&yh, g_yh);
    cudaGetSymbolAddress((void**)&yl, g_yl);

    __half *wa_h, *wa_l, *wp_h, *wp_l, *wf_h, *wf_l, *wq_h, *wq_l, *lm_h, *lm_l;
    cudaGetSymbolAddress((void**)&wa_h, g_wa_h);
    cudaGetSymbolAddress((void**)&wa_l, g_wa_l);
    cudaGetSymbolAddress((void**)&wp_h, g_wp_h);
    cudaGetSymbolAddress((void**)&wp_l, g_wp_l);
    cudaGetSymbolAddress((void**)&wf_h, g_wf_h);
    cudaGetSymbolAddress((void**)&wf_l, g_wf_l);
    cudaGetSymbolAddress((void**)&wq_h, g_wq_h);
    cudaGetSymbolAddress((void**)&wq_l, g_wq_l);
    cudaGetSymbolAddress((void**)&lm_h, g_lm_h);
    cudaGetSymbolAddress((void**)&lm_l, g_lm_l);

    cudaFuncSetAttribute(gemm_nt, cudaFuncAttributeMaxDynamicSharedMemorySize,
                         GSMEM_BYTES);

    dim3 tb(32, 8);
    transpose_split<<<dim3(2304 / 32, 768 / 32, 12), tb>>>(attn_w, wa_h, wa_l, NC, 3 * NC);
    transpose_split<<<dim3(768 / 32, 768 / 32, 12), tb>>>(proj_w, wp_h, wp_l, NC, NC);
    transpose_split<<<dim3(3072 / 32, 768 / 32, 12), tb>>>(fc_w, wf_h, wf_l, NC, 4 * NC);
    transpose_split<<<dim3(768 / 32, 3072 / 32, 12), tb>>>(fcp_w, wq_h, wq_l, 4 * NC, NC);
    split_kernel<<<(NV * NC + 255) / 256, 256>>>(lmh, lm_h, lm_l, NV * NC);

    embed_kernel<<<NTOK, 256>>>(idx, wte, wpe, x);

    for (int l = 0; l < NL; l++) {
        ln_kernel<<<NTOK, 256>>>(x, ln1_w + l * NC, ln1_b + l * NC, xh, xl);
        gemm_nt<<<dim3(NTOK / GBM, (3 * NC) / GBN), 256, GSMEM_BYTES>>>(
            xh, xl, wa_h + (size_t)l * 3 * NC * NC, wa_l + (size_t)l * 3 * NC * NC,
            attn_b + (size_t)l * 3 * NC, nullptr, qkv, nullptr, nullptr,
            NTOK, 3 * NC, NC, 0, 3);
        {
            dim3 grid(NT, NH, NB);
            attn_kernel<<<grid, 128>>>(qkv, xh, xl);
        }
        gemm_nt<<<dim3(NTOK / GBM, NC / GBN), 256, GSMEM_BYTES>>>(
            xh, xl, wp_h + (size_t)l * NC * NC, wp_l + (size_t)l * NC * NC,
            proj_b + (size_t)l * NC, x, x, nullptr, nullptr,
            NTOK, NC, NC, 0, 3);
        ln_kernel<<<NTOK, 256>>>(x, ln2_w + l * NC, ln2_b + l * NC, xh, xl);
        gemm_nt<<<dim3(NTOK / GBM, (4 * NC) / GBN), 256, GSMEM_BYTES>>>(
            xh, xl, wf_h + (size_t)l * 4 * NC * NC, wf_l + (size_t)l * 4 * NC * NC,
            fc_b + (size_t)l * 4 * NC, nullptr, nullptr, yh, yl,
            NTOK, 4 * NC, NC, 1, 3);
        gemm_nt<<<dim3(NTOK / GBM, NC / GBN), 256, GSMEM_BYTES>>>(
            yh, yl, wq_h + (size_t)l * NC * 4 * NC, wq_l + (size_t)l * NC * 4 * NC,
            fcp_b + (size_t)l * NC, x, x, nullptr, nullptr,
            NTOK, NC, 4 * NC, 0, 3);
    }

    ln_kernel<<<NTOK, 256>>>(x, lnf_w, lnf_b, xh, xl);

    // lm_head: 2-pass split (final op, no amplification)
    gemm_nt<<<dim3(NTOK / GBM, (NV + GBN - 1) / GBN), 256, GSMEM_BYTES>>>(
        xh, xl, lm_h, lm_l, nullptr, nullptr, out, nullptr, nullptr,
        NTOK, NV, NC, 0, 2);
}